// round 10
// baseline (speedup 1.0000x reference)
#include <cuda_runtime.h>
#include <math.h>
#include <stdint.h>

#define NTOK 2048
#define DDIM 1024
#define NEXP 8
#define FDIM 2048
#define NASS (NTOK * 2)

// GEMM tiling
#define BM 128
#define BN 128
#define BK 32          // K per chunk; 4 mma K=8 slices
#define NKS 4          // BK/8

// fragment-major smem layout (SINGLE stage; occupancy 2):
//  A: 32 groups (MI 0..7 x ks 0..3), each group 33 x 16B
//  B: 64 groups (NI 0..15 x ks 0..3), each group 33 x 8B
#define A_BUF_BYTES (32 * 33 * 16)     // 16896
#define B_BUF_BYTES (64 * 33 * 8)      // 16896
#define STAGE_BYTES (A_BUF_BYTES + B_BUF_BYTES)   // 33792
#define SM_META     STAGE_BYTES
#define SM_TOTAL    (SM_META + 512 * 3)           // 35328 -> 2 CTAs/SM

// ---------------- scratch (device globals) ---------------------------------
__device__ int   g_cnt[NEXP];
__device__ int   g_rows[NEXP][NTOK];
__device__ float g_gate[NASS];
__device__ float g_act[(size_t)NASS * FDIM];   // 32 MB
__device__ float g_y[(size_t)NASS * DDIM];     // 16 MB

// ---------------- helpers ---------------------------------------------------
__device__ __forceinline__ unsigned f2tf(float f) {   // RNA fp32 -> tf32 bits
    unsigned u;
    asm("cvt.rna.tf32.f32 %0, %1;" : "=r"(u) : "f"(f));
    return u;
}
__device__ __forceinline__ void mma_tf32(float* c, const unsigned* a, const unsigned* b) {
    asm volatile(
        "mma.sync.aligned.m16n8k8.row.col.f32.tf32.tf32.f32 "
        "{%0,%1,%2,%3}, {%4,%5,%6,%7}, {%8,%9}, {%0,%1,%2,%3};"
        : "+f"(c[0]), "+f"(c[1]), "+f"(c[2]), "+f"(c[3])
        : "r"(a[0]), "r"(a[1]), "r"(a[2]), "r"(a[3]), "r"(b[0]), "r"(b[1]));
}

// ---------------- kernel 0: zero expert counters ---------------------------
__global__ void k_zero() {
    if (threadIdx.x < NEXP) g_cnt[threadIdx.x] = 0;
}

// ---------------- kernel 1: router (one warp per token) --------------------
__global__ void k_router(const float* __restrict__ x, const float* __restrict__ Wr) {
    int warp = (blockIdx.x * blockDim.x + threadIdx.x) >> 5;
    int lane = threadIdx.x & 31;
    if (warp >= NTOK) return;
    const float* xr = x + (size_t)warp * DDIM;

    float acc[NEXP];
#pragma unroll
    for (int e = 0; e < NEXP; e++) acc[e] = 0.f;
    for (int i = lane; i < DDIM; i += 32) {
        float xv = xr[i];
#pragma unroll
        for (int e = 0; e < NEXP; e++) acc[e] += xv * Wr[e * DDIM + i];
    }
#pragma unroll
    for (int e = 0; e < NEXP; e++) {
#pragma unroll
        for (int off = 16; off; off >>= 1)
            acc[e] += __shfl_xor_sync(0xffffffffu, acc[e], off);
    }
    if (lane == 0) {
        int i0 = 0;
#pragma unroll
        for (int e = 1; e < NEXP; e++)
            if (acc[e] > acc[i0]) i0 = e;
        int i1 = -1;
#pragma unroll
        for (int e = 0; e < NEXP; e++) {
            if (e == i0) continue;
            if (i1 < 0 || acc[e] > acc[i1]) i1 = e;
        }
        float ex  = expf(acc[i1] - acc[i0]);
        float inv = 1.f / (1.f + ex);
        int p0 = atomicAdd(&g_cnt[i0], 1);
        g_rows[i0][p0] = 2 * warp;
        int p1 = atomicAdd(&g_cnt[i1], 1);
        g_rows[i1][p1] = 2 * warp + 1;
        g_gate[2 * warp]     = inv;
        g_gate[2 * warp + 1] = ex * inv;
    }
}

// ---------------- grouped GEMM: legacy mma.sync tf32, frag-major smem ------
// Per-CTA 128x128 tile; 8 warps in 2(m) x 4(n); per-warp 64x32.
// Single-buffered stage; 2 CTAs/SM hide the exposed STS + barrier phases.
template <int KTOT, int ROWSHIFT, int CSTRIDE, bool SQRELU, bool GATE>
__global__ __launch_bounds__(256, 2)
void k_gemm(const float* __restrict__ Asrc, const float* __restrict__ Bsrc) {
    extern __shared__ char smem[];
    const int e   = blockIdx.z;
    const int cnt = g_cnt[e];
    const int m0  = blockIdx.y * BM;
    if (m0 >= cnt) return;
    const int n0  = blockIdx.x * BN;
    const int tid  = threadIdx.x;
    const int wid  = tid >> 5;
    const int lane = tid & 31;
    const int g    = lane >> 2;
    const int t    = lane & 3;
    const int wm   = wid >> 2;     // 0..1
    const int wn   = wid & 3;      // 0..3

    int*   s_a   = (int*)(smem + SM_META);
    int*   s_row = (int*)(smem + SM_META + 512);
    float* s_g   = (float*)(smem + SM_META + 1024);

    const float* Aptr = (ROWSHIFT == 1) ? Asrc : g_act;
    float*       Cptr = SQRELU ? g_act : g_y;

    if (tid < BM) {
        int idx = m0 + tid;
        int aid = g_rows[e][idx < cnt ? idx : cnt - 1];
        s_a[tid]   = aid;
        s_row[tid] = aid >> ROWSHIFT;
        if (GATE) s_g[tid] = g_gate[aid];
    }
    __syncthreads();

    const float* Bslab = Bsrc + (size_t)e * CSTRIDE * KTOT + (size_t)n0 * KTOT;

    // ---- staging precompute: 4 float4 chunks each for A and B per thread ----
    // c4 = tid + 256*i : row = c4>>3 (0..127), kq = c4&7 (k = 4*kq within BK=32)
    const float* asrc[4]; uint32_t aoff[4];
    const float* bsrc[4]; uint32_t boff[4];
#pragma unroll
    for (int i = 0; i < 4; i++) {
        int c4  = tid + 256 * i;
        int row = c4 >> 3, kq = c4 & 7;
        int ks = kq >> 1, p = kq & 1;
        {   // A: frag slot for (row, k): reg r = h + 2p, lane' = 4*(gg^(ks>>1)) + j
            int MI = row >> 4, h = (row >> 3) & 1, gg = row & 7;
            int ge = gg ^ (ks >> 1);
            aoff[i] = (uint32_t)(((MI * 4 + ks) * 33 + 4 * ge) * 16 + (h + 2 * p) * 4);
            asrc[i] = Aptr + (size_t)s_row[row] * KTOT + 4 * kq;
        }
        {   // B: group NI*4+ks, lane = 4*gg + j, slot p
            int NI = row >> 3, gg = row & 7;
            boff[i] = (uint32_t)(((NI * 4 + ks) * 33 + 4 * gg) * 8 + p * 4);
            bsrc[i] = Bslab + (size_t)row * KTOT + 4 * kq;
        }
    }

    float4 ra[4], rb[4];
    auto LDG = [&](int c) {
        const int k0 = c * BK;
#pragma unroll
        for (int i = 0; i < 4; i++) ra[i] = *(const float4*)(asrc[i] + k0);
#pragma unroll
        for (int i = 0; i < 4; i++) rb[i] = *(const float4*)(bsrc[i] + k0);
    };
    auto STS = [&]() {
        char* stA = smem;
        char* stB = smem + A_BUF_BYTES;
#pragma unroll
        for (int i = 0; i < 4; i++) {
            const float* v = &ra[i].x;
#pragma unroll
            for (int j = 0; j < 4; j++)
                *(uint32_t*)(stA + aoff[i] + j * 16) = f2tf(v[j]);
        }
#pragma unroll
        for (int i = 0; i < 4; i++) {
            const float* v = &rb[i].x;
#pragma unroll
            for (int j = 0; j < 4; j++)
                *(uint32_t*)(stB + boff[i] + j * 8) = f2tf(v[j]);
        }
    };

    float cacc[4][4][4];
#pragma unroll
    for (int mi = 0; mi < 4; mi++)
#pragma unroll
        for (int ni = 0; ni < 4; ni++)
#pragma unroll
            for (int r = 0; r < 4; r++) cacc[mi][ni][r] = 0.f;

    constexpr int NC = KTOT / BK;
    LDG(0);
    STS();
    __syncthreads();

    for (int c = 0; c < NC; c++) {
        if (c + 1 < NC) LDG(c + 1);      // prefetch next chunk into registers

        const char* Abuf = smem;
        const char* Bbuf = smem + A_BUF_BYTES;
#pragma unroll
        for (int ks = 0; ks < NKS; ks++) {
            const int laneA = lane ^ ((ks >> 1) << 2);
            uint4 af[4]; uint2 bf[4];
#pragma unroll
            for (int mi = 0; mi < 4; mi++) {
                int MI = wm * 4 + mi;
                af[mi] = *(const uint4*)(Abuf + ((MI * 4 + ks) * 33 + laneA) * 16);
            }
#pragma unroll
            for (int ni = 0; ni < 4; ni++) {
                int NI = wn * 4 + ni;
                bf[ni] = *(const uint2*)(Bbuf + ((NI * 4 + ks) * 33 + lane) * 8);
            }
#pragma unroll
            for (int mi = 0; mi < 4; mi++)
#pragma unroll
                for (int ni = 0; ni < 4; ni++)
                    mma_tf32(cacc[mi][ni], &af[mi].x, &bf[ni].x);
        }

        __syncthreads();                 // all readers done with the buffer
        if (c + 1 < NC) {
            STS();                       // refill (exposed; hidden by co-CTA)
            __syncthreads();
        }
    }

    // ---- epilogue: direct STG from accumulators ----
#pragma unroll
    for (int mi = 0; mi < 4; mi++) {
#pragma unroll
        for (int ni = 0; ni < 4; ni++) {
            const float* c = cacc[mi][ni];
            int rb_ = wm * 64 + mi * 16;
            int cb  = wn * 32 + ni * 8 + 2 * t;
#pragma unroll
            for (int h = 0; h < 2; h++) {
                int r = rb_ + g + h * 8;
                if (m0 + r < cnt) {
                    int aid = s_a[r];
                    float gv = GATE ? s_g[r] : 0.f;
#pragma unroll
                    for (int q = 0; q < 2; q++) {
                        float v = c[h * 2 + q];
                        if (SQRELU) v = (v > 0.f) ? v * v : 0.f;
                        if (GATE) v *= gv;
                        Cptr[(size_t)aid * CSTRIDE + n0 + cb + q] = v;
                    }
                }
            }
        }
    }
}

// ---------------- kernel 4: combine the two gated expert outputs -----------
__global__ void k_combine(float* __restrict__ out) {
    int i = blockIdx.x * blockDim.x + threadIdx.x;
    if (i >= NTOK * DDIM / 4) return;
    int n  = i / (DDIM / 4);
    int d4 = i % (DDIM / 4);
    const float4 a = *((const float4*)(g_y + (size_t)(2 * n) * DDIM) + d4);
    const float4 b = *((const float4*)(g_y + (size_t)(2 * n + 1) * DDIM) + d4);
    float4 o;
    o.x = a.x + b.x;
    o.y = a.y + b.y;
    o.z = a.z + b.z;
    o.w = a.w + b.w;
    *((float4*)(out + (size_t)n * DDIM) + d4) = o;
}

// ---------------- launch ----------------------------------------------------
extern "C" void kernel_launch(void* const* d_in, const int* in_sizes, int n_in,
                              void* d_out, int out_size) {
    const float* x  = (const float*)d_in[0];   // [2048, 1024]
    const float* Wr = (const float*)d_in[1];   // [8, 1024]
    const float* W1 = (const float*)d_in[2];   // [8, 2048, 1024]
    const float* W2 = (const float*)d_in[3];   // [8, 1024, 2048]
    float* out = (float*)d_out;                // [2048, 1024]
    (void)in_sizes; (void)n_in; (void)out_size;

    cudaFuncSetAttribute((const void*)k_gemm<DDIM, 1, FDIM, true, false>,
                         cudaFuncAttributeMaxDynamicSharedMemorySize, SM_TOTAL);
    cudaFuncSetAttribute((const void*)k_gemm<FDIM, 0, DDIM, false, true>,
                         cudaFuncAttributeMaxDynamicSharedMemorySize, SM_TOTAL);

    k_zero<<<1, 32>>>();
    k_router<<<NTOK / 8, 256>>>(x, Wr);

    // fc1: act[a, f] = relu(x[a>>1] . W1[e][f])^2
    k_gemm<DDIM, 1, FDIM, true, false>
        <<<dim3(FDIM / BN, NTOK / BM, NEXP), 256, SM_TOTAL>>>(x, W1);

    // fc2: y[a, d] = gate[a] * (act[a] . W2[e][d])
    k_gemm<FDIM, 0, DDIM, false, true>
        <<<dim3(DDIM / BN, NTOK / BM, NEXP), 256, SM_TOTAL>>>(nullptr, W2);

    k_combine<<<(NTOK * DDIM / 4 + 255) / 256, 256>>>(out);
}

// round 11
// speedup vs baseline: 1.1067x; 1.1067x over previous
#include <cuda_runtime.h>
#include <math.h>
#include <stdint.h>

#define NTOK 2048
#define DDIM 1024
#define NEXP 8
#define FDIM 2048
#define NASS (NTOK * 2)

// GEMM tiling: CTA 128x256, warp 64x32 (16 warps = 512 threads), BK=32
#define BM 128
#define BN 256
#define BK 32
#define NKS 4          // BK/8
#define THREADS 512

// fragment-major smem layout (double-buffered):
//  A: 32 groups (MI 0..7 x ks 0..3), each 33 x 16B lines
//  B: 128 groups (NI 0..31 x ks 0..3), each 33 x 8B lines
#define A_BUF_BYTES (32 * 33 * 16)      // 16896
#define B_BUF_BYTES (128 * 33 * 8)      // 33792
#define STAGE_BYTES (A_BUF_BYTES + B_BUF_BYTES)   // 50688
#define SM_META     (2 * STAGE_BYTES)             // 101376
#define SM_TOTAL    (SM_META + 512 * 3)           // 102912 (1 CTA/SM)

// ---------------- scratch (device globals) ---------------------------------
__device__ int   g_cnt[NEXP];
__device__ int   g_rows[NEXP][NTOK];
__device__ float g_gate[NASS];
__device__ float g_act[(size_t)NASS * FDIM];   // 32 MB
__device__ float g_y[(size_t)NASS * DDIM];     // 16 MB

// ---------------- helpers ---------------------------------------------------
__device__ __forceinline__ unsigned f2tf(float f) {   // RNA fp32 -> tf32 bits
    unsigned u;
    asm("cvt.rna.tf32.f32 %0, %1;" : "=r"(u) : "f"(f));
    return u;
}
__device__ __forceinline__ void mma_tf32(float* c, const unsigned* a, const unsigned* b) {
    asm volatile(
        "mma.sync.aligned.m16n8k8.row.col.f32.tf32.tf32.f32 "
        "{%0,%1,%2,%3}, {%4,%5,%6,%7}, {%8,%9}, {%0,%1,%2,%3};"
        : "+f"(c[0]), "+f"(c[1]), "+f"(c[2]), "+f"(c[3])
        : "r"(a[0]), "r"(a[1]), "r"(a[2]), "r"(a[3]), "r"(b[0]), "r"(b[1]));
}

// ---------------- kernel 0: zero expert counters ---------------------------
__global__ void k_zero() {
    if (threadIdx.x < NEXP) g_cnt[threadIdx.x] = 0;
}

// ---------------- kernel 1: router (one warp per token) --------------------
__global__ void k_router(const float* __restrict__ x, const float* __restrict__ Wr) {
    int warp = (blockIdx.x * blockDim.x + threadIdx.x) >> 5;
    int lane = threadIdx.x & 31;
    if (warp >= NTOK) return;
    const float* xr = x + (size_t)warp * DDIM;

    float acc[NEXP];
#pragma unroll
    for (int e = 0; e < NEXP; e++) acc[e] = 0.f;
    for (int i = lane; i < DDIM; i += 32) {
        float xv = xr[i];
#pragma unroll
        for (int e = 0; e < NEXP; e++) acc[e] += xv * Wr[e * DDIM + i];
    }
#pragma unroll
    for (int e = 0; e < NEXP; e++) {
#pragma unroll
        for (int off = 16; off; off >>= 1)
            acc[e] += __shfl_xor_sync(0xffffffffu, acc[e], off);
    }
    if (lane == 0) {
        int i0 = 0;
#pragma unroll
        for (int e = 1; e < NEXP; e++)
            if (acc[e] > acc[i0]) i0 = e;
        int i1 = -1;
#pragma unroll
        for (int e = 0; e < NEXP; e++) {
            if (e == i0) continue;
            if (i1 < 0 || acc[e] > acc[i1]) i1 = e;
        }
        float ex  = expf(acc[i1] - acc[i0]);
        float inv = 1.f / (1.f + ex);
        int p0 = atomicAdd(&g_cnt[i0], 1);
        g_rows[i0][p0] = 2 * warp;
        int p1 = atomicAdd(&g_cnt[i1], 1);
        g_rows[i1][p1] = 2 * warp + 1;
        g_gate[2 * warp]     = inv;
        g_gate[2 * warp + 1] = ex * inv;
    }
}

// ---------------- grouped GEMM: legacy mma.sync tf32, frag-major smem ------
// CTA 128x256; 16 warps in 2(m) x 8(n); per-warp 64x32. Double-buffered,
// one __syncthreads per chunk; register prefetch of the next chunk.
template <int KTOT, int ROWSHIFT, int CSTRIDE, bool SQRELU, bool GATE>
__global__ __launch_bounds__(THREADS, 1)
void k_gemm(const float* __restrict__ Asrc, const float* __restrict__ Bsrc) {
    extern __shared__ char smem[];
    const int e   = blockIdx.z;
    const int cnt = g_cnt[e];
    const int m0  = blockIdx.y * BM;
    if (m0 >= cnt) return;
    const int n0  = blockIdx.x * BN;
    const int tid  = threadIdx.x;
    const int wid  = tid >> 5;
    const int lane = tid & 31;
    const int g    = lane >> 2;
    const int t    = lane & 3;
    const int wm   = wid >> 3;     // 0..1
    const int wn   = wid & 7;      // 0..7

    int*   s_a   = (int*)(smem + SM_META);
    int*   s_row = (int*)(smem + SM_META + 512);
    float* s_g   = (float*)(smem + SM_META + 1024);

    const float* Aptr = (ROWSHIFT == 1) ? Asrc : g_act;
    float*       Cptr = SQRELU ? g_act : g_y;

    if (tid < BM) {
        int idx = m0 + tid;
        int aid = g_rows[e][idx < cnt ? idx : cnt - 1];
        s_a[tid]   = aid;
        s_row[tid] = aid >> ROWSHIFT;
        if (GATE) s_g[tid] = g_gate[aid];
    }
    __syncthreads();

    const float* Bslab = Bsrc + (size_t)e * CSTRIDE * KTOT + (size_t)n0 * KTOT;

    // ---- staging precompute ----
    // A: 1024 float4 chunks -> 2/thread. c4 = tid + 512*i : row=c4>>3, kq=c4&7
    // B: 2048 float4 chunks -> 4/thread. row up to 255.
    const float* asrc[2]; uint32_t aoff[2];
    const float* bsrc[4]; uint32_t boff[4];
#pragma unroll
    for (int i = 0; i < 2; i++) {
        int c4  = tid + THREADS * i;
        int row = c4 >> 3, kq = c4 & 7;
        int ks = kq >> 1, p = kq & 1;
        int MI = row >> 4, h = (row >> 3) & 1, gg = row & 7;
        int ge = gg ^ (ks >> 1);
        aoff[i] = (uint32_t)(((MI * 4 + ks) * 33 + 4 * ge) * 16 + (h + 2 * p) * 4);
        asrc[i] = Aptr + (size_t)s_row[row] * KTOT + 4 * kq;
    }
#pragma unroll
    for (int i = 0; i < 4; i++) {
        int c4  = tid + THREADS * i;
        int row = c4 >> 3, kq = c4 & 7;
        int ks = kq >> 1, p = kq & 1;
        int NI = row >> 3, gg = row & 7;
        boff[i] = (uint32_t)(((NI * 4 + ks) * 33 + 4 * gg) * 8 + p * 4);
        bsrc[i] = Bslab + (size_t)row * KTOT + 4 * kq;
    }

    float4 ra[2], rb[4];
    auto LDG = [&](int c) {
        const int k0 = c * BK;
#pragma unroll
        for (int i = 0; i < 2; i++) ra[i] = *(const float4*)(asrc[i] + k0);
#pragma unroll
        for (int i = 0; i < 4; i++) rb[i] = *(const float4*)(bsrc[i] + k0);
    };
    auto STS = [&](int s) {      // s = buffer parity
        char* stA = smem + s * STAGE_BYTES;
        char* stB = stA + A_BUF_BYTES;
#pragma unroll
        for (int i = 0; i < 2; i++) {
            const float* v = &ra[i].x;
#pragma unroll
            for (int j = 0; j < 4; j++)
                *(uint32_t*)(stA + aoff[i] + j * 16) = f2tf(v[j]);
        }
#pragma unroll
        for (int i = 0; i < 4; i++) {
            const float* v = &rb[i].x;
#pragma unroll
            for (int j = 0; j < 4; j++)
                *(uint32_t*)(stB + boff[i] + j * 8) = f2tf(v[j]);
        }
    };

    float cacc[4][4][4];
#pragma unroll
    for (int mi = 0; mi < 4; mi++)
#pragma unroll
        for (int ni = 0; ni < 4; ni++)
#pragma unroll
            for (int r = 0; r < 4; r++) cacc[mi][ni][r] = 0.f;

    constexpr int NC = KTOT / BK;
    LDG(0);
    STS(0);
    __syncthreads();

    for (int c = 0; c < NC; c++) {
        if (c + 1 < NC) LDG(c + 1);      // prefetch next chunk into registers

        const char* Abuf = smem + (c & 1) * STAGE_BYTES;
        const char* Bbuf = Abuf + A_BUF_BYTES;
#pragma unroll
        for (int ks = 0; ks < NKS; ks++) {
            const int laneA = lane ^ ((ks >> 1) << 2);
            uint4 af[4]; uint2 bf[4];
#pragma unroll
            for (int mi = 0; mi < 4; mi++) {
                int MI = wm * 4 + mi;
                af[mi] = *(const uint4*)(Abuf + ((MI * 4 + ks) * 33 + laneA) * 16);
            }
#pragma unroll
            for (int ni = 0; ni < 4; ni++) {
                int NI = wn * 4 + ni;
                bf[ni] = *(const uint2*)(Bbuf + ((NI * 4 + ks) * 33 + lane) * 8);
            }
#pragma unroll
            for (int mi = 0; mi < 4; mi++)
#pragma unroll
                for (int ni = 0; ni < 4; ni++)
                    mma_tf32(cacc[mi][ni], &af[mi].x, &bf[ni].x);
        }

        if (c + 1 < NC) STS((c + 1) & 1);   // other buffer; readers done at sync(c-1)
        __syncthreads();
    }

    // ---- epilogue: direct STG from accumulators ----
#pragma unroll
    for (int mi = 0; mi < 4; mi++) {
#pragma unroll
        for (int ni = 0; ni < 4; ni++) {
            const float* c = cacc[mi][ni];
            int rb_ = wm * 64 + mi * 16;
            int cb  = wn * 32 + ni * 8 + 2 * t;
#pragma unroll
            for (int h = 0; h < 2; h++) {
                int r = rb_ + g + h * 8;
                if (m0 + r < cnt) {
                    int aid = s_a[r];
                    float gv = GATE ? s_g[r] : 0.f;
#pragma unroll
                    for (int q = 0; q < 2; q++) {
                        float v = c[h * 2 + q];
                        if (SQRELU) v = (v > 0.f) ? v * v : 0.f;
                        if (GATE) v *= gv;
                        Cptr[(size_t)aid * CSTRIDE + n0 + cb + q] = v;
                    }
                }
            }
        }
    }
}

// ---------------- kernel 4: combine the two gated expert outputs -----------
__global__ void k_combine(float* __restrict__ out) {
    int i = blockIdx.x * blockDim.x + threadIdx.x;
    if (i >= NTOK * DDIM / 4) return;
    int n  = i / (DDIM / 4);
    int d4 = i % (DDIM / 4);
    const float4 a = *((const float4*)(g_y + (size_t)(2 * n) * DDIM) + d4);
    const float4 b = *((const float4*)(g_y + (size_t)(2 * n + 1) * DDIM) + d4);
    float4 o;
    o.x = a.x + b.x;
    o.y = a.y + b.y;
    o.z = a.z + b.z;
    o.w = a.w + b.w;
    *((float4*)(out + (size_t)n * DDIM) + d4) = o;
}

// ---------------- launch ----------------------------------------------------
extern "C" void kernel_launch(void* const* d_in, const int* in_sizes, int n_in,
                              void* d_out, int out_size) {
    const float* x  = (const float*)d_in[0];   // [2048, 1024]
    const float* Wr = (const float*)d_in[1];   // [8, 1024]
    const float* W1 = (const float*)d_in[2];   // [8, 2048, 1024]
    const float* W2 = (const float*)d_in[3];   // [8, 1024, 2048]
    float* out = (float*)d_out;                // [2048, 1024]
    (void)in_sizes; (void)n_in; (void)out_size;

    cudaFuncSetAttribute((const void*)k_gemm<DDIM, 1, FDIM, true, false>,
                         cudaFuncAttributeMaxDynamicSharedMemorySize, SM_TOTAL);
    cudaFuncSetAttribute((const void*)k_gemm<FDIM, 0, DDIM, false, true>,
                         cudaFuncAttributeMaxDynamicSharedMemorySize, SM_TOTAL);

    k_zero<<<1, 32>>>();
    k_router<<<NTOK / 8, 256>>>(x, Wr);

    // fc1: act[a, f] = relu(x[a>>1] . W1[e][f])^2
    k_gemm<DDIM, 1, FDIM, true, false>
        <<<dim3(FDIM / BN, NTOK / BM, NEXP), THREADS, SM_TOTAL>>>(x, W1);

    // fc2: y[a, d] = gate[a] * (act[a] . W2[e][d])
    k_gemm<FDIM, 0, DDIM, false, true>
        <<<dim3(DDIM / BN, NTOK / BM, NEXP), THREADS, SM_TOTAL>>>(nullptr, W2);

    k_combine<<<(NTOK * DDIM / 4 + 255) / 256, 256>>>(out);
}